// round 5
// baseline (speedup 1.0000x reference)
#include <cuda_runtime.h>
#include <cstdint>

#define S_LEN 4096
#define D_MODEL 256
#define QPW 2                 // queries per warp, interleaved in one sweep
#define QPB (8 * QPW)         // 16 queries per block
#define NTHREADS 256

__device__ __forceinline__ float ex2f(float a) {
    float r; asm("ex2.approx.f32 %0,%1;" : "=f"(r) : "f"(a)); return r;
}

// One key (s = -lam2*size_t, h = height_t) against one query. 5 fma-pipe + 1 MUFU.
__device__ __forceinline__ void proc1(float s, float h,
                                      float qsz, float a2, float nM2,
                                      float& z, float& r)
{
    float d  = qsz + s;                    // FADD
    float tv = fmaf(a2, h, nM2);           // FFMA
    float p  = ex2f(tv - fabsf(d));        // FADD (|d| folded as src modifier) + MUFU
    z += p;                                // FADD
    r = fmaf(p, h, r);                     // FFMA
}

__global__ __launch_bounds__(NTHREADS) void dwsa_kernel(
    const float2* __restrict__ x,   // [B, S, 2] (size, height)
    const float* __restrict__ Wq,
    const float* __restrict__ Wk,
    const float* __restrict__ Wv,
    float* __restrict__ out)        // [B, S, 256]
{
    __shared__ float nsz[S_LEN];    // -lam2 * size  (16 KB)
    __shared__ float hh [S_LEN];    // height        (16 KB)
    __shared__ float red[24];

    const int tid  = threadIdx.x;
    const int lane = tid & 31;
    const int warp = tid >> 5;
    const int blocks_per_batch = S_LEN / QPB;
    const int b  = blockIdx.x / blocks_per_batch;
    const int q0 = (blockIdx.x % blocks_per_batch) * QPB;

    const float LOG2E = 1.4426950408889634f;
    const float LAM2  = 0.5f * LOG2E;

    // --- Stage batch (SoA), track h min/max, detect exact-zero heights ---
    const float2* xb = x + (size_t)b * S_LEN;
    float hmax = -1e30f, hmin = 1e30f;
    int zflag = 0;
    for (int i = tid; i < S_LEN; i += NTHREADS) {
        float2 v = xb[i];
        nsz[i] = -LAM2 * v.x;
        hh[i]  = v.y;
        hmax = fmaxf(hmax, v.y);
        hmin = fminf(hmin, v.y);
        zflag |= (v.y == 0.0f);
    }
    float cp = Wq[tid] * Wk[tid];           // NTHREADS == D_MODEL
    #pragma unroll
    for (int o = 16; o > 0; o >>= 1) {
        hmax = fmaxf(hmax, __shfl_xor_sync(0xffffffffu, hmax, o));
        hmin = fminf(hmin, __shfl_xor_sync(0xffffffffu, hmin, o));
        cp  += __shfl_xor_sync(0xffffffffu, cp, o);
    }
    if (lane == 0) { red[warp] = hmax; red[8 + warp] = hmin; red[16 + warp] = cp; }
    const int anyzero = __syncthreads_or(zflag);
    hmax = red[0]; hmin = red[8];
    float csum = red[16];
    #pragma unroll
    for (int w = 1; w < 8; w++) {
        hmax = fmaxf(hmax, red[w]);
        hmin = fminf(hmin, red[8 + w]);
        csum += red[16 + w];
    }
    const float c = csum * (1.0f / 16.0f);

    // --- Two queries per warp, interleaved over one key sweep ---
    const int sA = q0 + warp;
    const int sB = q0 + warp + 8;
    const float qszA = -nsz[sA], hsA = hh[sA];
    const float qszB = -nsz[sB], hsB = hh[sB];
    const float a2A  = c * hsA * LOG2E;
    const float a2B  = c * hsB * LOG2E;
    const float nM2A = -fmaxf(a2A * hmax, a2A * hmin);
    const float nM2B = -fmaxf(a2B * hmax, a2B * hmin);

    float zv[QPW], rv[QPW];

    if (!anyzero) {
        const float4* nsz4 = (const float4*)nsz;
        const float4* hh4  = (const float4*)hh;
        // split accumulators (even/odd components) for FADD-chain ILP
        float zA0 = 0.f, zA1 = 0.f, rA0 = 0.f, rA1 = 0.f;
        float zB0 = 0.f, zB1 = 0.f, rB0 = 0.f, rB1 = 0.f;

        #pragma unroll 4
        for (int ch = 0; ch < S_LEN / 128; ch++) {
            const int idx = lane + ch * 32;
            float4 s4 = nsz4[idx];          // LDS.128
            float4 h4 = hh4[idx];           // LDS.128
            proc1(s4.x, h4.x, qszA, a2A, nM2A, zA0, rA0);
            proc1(s4.y, h4.y, qszA, a2A, nM2A, zA1, rA1);
            proc1(s4.z, h4.z, qszA, a2A, nM2A, zA0, rA0);
            proc1(s4.w, h4.w, qszA, a2A, nM2A, zA1, rA1);
            proc1(s4.x, h4.x, qszB, a2B, nM2B, zB0, rB0);
            proc1(s4.y, h4.y, qszB, a2B, nM2B, zB1, rB1);
            proc1(s4.z, h4.z, qszB, a2B, nM2B, zB0, rB0);
            proc1(s4.w, h4.w, qszB, a2B, nM2B, zB1, rB1);
        }
        zv[0] = zA0 + zA1;  rv[0] = rA0 + rA1;
        zv[1] = zB0 + zB1;  rv[1] = rB0 + rB1;
    } else {
        // Masked fallback (rare): scalar with key mask
        #pragma unroll
        for (int qi = 0; qi < QPW; qi++) {
            const float qsz = qi ? qszB : qszA;
            const float a2  = qi ? a2B  : a2A;
            const float nM2 = qi ? nM2B : nM2A;
            float zz = 0.f, rr = 0.f;
            for (int t = lane; t < S_LEN; t += 32) {
                float ht = hh[t];
                float d  = qsz + nsz[t];
                float p  = ex2f(fmaf(a2, ht, nM2) - fabsf(d));
                if (ht == 0.f) p = 0.f;
                zz += p; rr = fmaf(p, ht, rr);
            }
            zv[qi] = zz; rv[qi] = rr;
        }
    }

    const float4* wv4 = (const float4*)Wv;
    #pragma unroll
    for (int qi = 0; qi < QPW; qi++) {
        float z = zv[qi], r = rv[qi];
        #pragma unroll
        for (int o = 16; o > 0; o >>= 1) {
            z += __shfl_xor_sync(0xffffffffu, z, o);
            r += __shfl_xor_sync(0xffffffffu, r, o);
        }
        const float val = (z > 0.f) ? __fdividef(r, z) : 0.f;
        const int s = q0 + warp + qi * 8;
        float4* o4 = (float4*)(out + ((size_t)b * S_LEN + s) * D_MODEL);
        #pragma unroll
        for (int k = 0; k < 2; k++) {
            float4 w = wv4[lane * 2 + k];
            o4[lane * 2 + k] = make_float4(val * w.x, val * w.y, val * w.z, val * w.w);
        }
    }
}

extern "C" void kernel_launch(void* const* d_in, const int* in_sizes, int n_in,
                              void* d_out, int out_size) {
    const float2* x  = (const float2*)d_in[0];
    const float*  Wq = (const float*)d_in[1];
    const float*  Wk = (const float*)d_in[2];
    const float*  Wv = (const float*)d_in[3];
    float* out = (float*)d_out;

    const int B = in_sizes[0] / (S_LEN * 2);
    const int grid = B * (S_LEN / QPB);
    dwsa_kernel<<<grid, NTHREADS>>>(x, Wq, Wk, Wv, out);
}